// round 9
// baseline (speedup 1.0000x reference)
#include <cuda_runtime.h>
#include <math.h>

#define Bn 8
#define Hn 192
#define Wn 192
#define NTOT (Bn*Hn*Wn)
#define NCH 6                     // 192 rows = 6 x u32 words
#define NW64 3                    // = 3 x u64 words

__device__ unsigned g_mask[2][Bn][NCH][Wn];   // fg bit per (row,col)
__device__ int      g_hasany[2][Bn][NCH];
__device__ float    g_part[Bn*Hn];
__device__ unsigned g_count = 0;

// ---------------------------------------------------------------------------
// Kernel A: per-column fg bitmasks. Block = (tensor, b, 32-row chunk),
// blockDim (192,2): each thread builds 16 bits; halves composed via shared.
// ---------------------------------------------------------------------------
__global__ void mask_kernel(const float* __restrict__ pred,
                            const float* __restrict__ tgt) {
    const int blk = blockIdx.x;               // t*48 + b*6 + chunk
    const int t = blk / (Bn * NCH);
    const int r = blk % (Bn * NCH);
    const int b = r / NCH;
    const int chunk = r % NCH;
    const float* src = t ? tgt : pred;
    const int w = threadIdx.x;
    const int y = threadIdx.y;                // 0 = low 16 rows, 1 = high 16
    const int h0 = chunk * 32 + y * 16;

    unsigned part = 0;
    #pragma unroll
    for (int i = 0; i < 16; ++i) {
        float v = src[(b * Hn + h0 + i) * Wn + w];
        bool fg = t ? (v > 0.5f) : (v > 0.0f);   // sigmoid(v)>0.5 <=> v>0
        part |= (unsigned)fg << i;
    }

    __shared__ unsigned sm[Wn];
    if (y == 0) sm[w] = part;
    int any = __syncthreads_or(part != 0u);      // barrier + OR
    if (y == 1) g_mask[t][b][chunk][w] = sm[w] | (part << 16);
    if (w == 0 && y == 0) g_hasany[t][b][chunk] = any;
}

// distance from row h to nearest set bit in 192-bit mask (3 u64); BIG if none
#define BIGD (1 << 20)
__device__ __forceinline__ int nearest_set64(const unsigned long long m[NW64], int h) {
    const int c = h >> 6, bit = h & 63;
    int down = BIGD, up = BIGD;

    unsigned long long x = m[c] & (~0ULL << bit);        // bits >= h
    if (x) down = (__ffsll(x) - 1) - bit;
    else {
        #pragma unroll
        for (int j = 1; j < NW64; ++j) {
            int jj = c + j;
            if (jj < NW64 && m[jj]) { down = (jj * 64 + __ffsll(m[jj]) - 1) - h; break; }
        }
    }
    x = m[c] & (~0ULL >> (63 - bit));                    // bits <= h
    if (x) up = bit - (63 - __clzll(x));
    else {
        #pragma unroll
        for (int j = 1; j < NW64; ++j) {
            int jj = c - j;
            if (jj >= 0 && m[jj]) { up = h - (jj * 64 + 63 - __clzll(m[jj])); break; }
        }
    }
    return min(up, down);
}

// ---------------------------------------------------------------------------
// Kernel B: column distances from bitmasks + exact windowed 1D row DT +
// fused loss + deterministic block reduction + last-block final reduce.
// One block per (b, h), thread = output column p.
// ---------------------------------------------------------------------------
__global__ void rowpass_kernel(const float* __restrict__ pred,
                               const float* __restrict__ tgt,
                               float* __restrict__ out) {
    const int b = blockIdx.x / Hn;
    const int h = blockIdx.x % Hn;
    const int p = threadIdx.x;

    __shared__ float ssq[4][Wn];
    __shared__ float wsum[6];
    __shared__ int   s_last;

    unsigned long long mp[NW64], mt[NW64], mpc[NW64], mtc[NW64];
    #pragma unroll
    for (int k = 0; k < NW64; ++k) {
        unsigned lo = g_mask[0][b][2*k][p],   hi = g_mask[0][b][2*k+1][p];
        mp[k] = (unsigned long long)lo | ((unsigned long long)hi << 32);
        mpc[k] = ~mp[k];
        lo = g_mask[1][b][2*k][p];  hi = g_mask[1][b][2*k+1][p];
        mt[k] = (unsigned long long)lo | ((unsigned long long)hi << 32);
        mtc[k] = ~mt[k];
    }
    int s0 = nearest_set64(mpc, h);   // pred fg EDT col dist (to nearest bg)
    int s1 = nearest_set64(mp,  h);   // pred bg EDT col dist (to nearest fg)
    int s2 = nearest_set64(mtc, h);
    int s3 = nearest_set64(mt,  h);
    ssq[0][p] = (s0 >= BIGD) ? 1.0e12f : (float)(s0 * s0);
    ssq[1][p] = (s1 >= BIGD) ? 1.0e12f : (float)(s1 * s1);
    ssq[2][p] = (s2 >= BIGD) ? 1.0e12f : (float)(s2 * s2);
    ssq[3][p] = (s3 >= BIGD) ? 1.0e12f : (float)(s3 * s3);
    __syncthreads();

    // exact min_q (p-q)^2 + s_q^2: all candidates at offset d are >= d^2,
    // so expanding outward and stopping at d^2 >= best is exact.
    float D[4];
    #pragma unroll
    for (int m = 0; m < 4; ++m) {
        float best = ssq[m][p];
        for (int d = 1; d < Wn; ++d) {
            float dd = (float)(d * d);
            if (dd >= best) break;
            int lo = p - d, hi = p + d;
            if (lo >= 0)  best = fminf(best, dd + ssq[m][lo]);
            if (hi < Wn)  best = fminf(best, dd + ssq[m][hi]);
        }
        D[m] = best;
    }

    int hp = 0, ht = 0;
    #pragma unroll
    for (int j = 0; j < NCH; ++j) {
        hp |= g_hasany[0][b][j];
        ht |= g_hasany[1][b][j];
    }

    float pd = (sqrtf(D[0]) + sqrtf(D[1])) * (float)hp;
    float td = (sqrtf(D[2]) + sqrtf(D[3])) * (float)ht;

    const int idx = (b * Hn + h) * Wn + p;
    float x  = pred[idx];
    float tv = tgt[idx];
    float sg = 1.0f / (1.0f + expf(-x));
    float e  = sg - tv;
    e = e * e;

    float num = pd * pd + td * td;
    float den = pd + td;
    den = den * den;
    float v = e * (num / den);

    // deterministic block reduction
    #pragma unroll
    for (int o = 16; o > 0; o >>= 1)
        v += __shfl_down_sync(0xffffffffu, v, o);
    if ((p & 31) == 0) wsum[p >> 5] = v;
    __syncthreads();
    if (p == 0) {
        float s = 0.0f;
        #pragma unroll
        for (int i = 0; i < 6; ++i) s += wsum[i];
        g_part[blockIdx.x] = s;
        __threadfence();
        unsigned ticket = atomicAdd(&g_count, 1u);
        s_last = (ticket == (unsigned)(gridDim.x - 1));
    }
    __syncthreads();

    // last finishing block performs the (deterministic, fixed-order) final
    // reduction in fp64 and resets the ticket counter for graph replay.
    if (s_last) {
        __shared__ double dsm[Wn];
        double s = 0.0;
        for (int i = p; i < Bn * Hn; i += Wn)
            s += (double)g_part[i];
        dsm[p] = s;
        __syncthreads();
        // 192 -> 96 -> 48 -> 24 -> 12 -> 6 -> 3, then sum the last 3 lanes.
        #pragma unroll
        for (int o = 96; o >= 3; o >>= 1) {
            if (p < o) dsm[p] += dsm[p + o];
            __syncthreads();
        }
        if (p == 0) {
            double tot = dsm[0] + dsm[1] + dsm[2];
            out[0] = (float)(tot / (double)NTOT);
            g_count = 0;
        }
    }
}

extern "C" void kernel_launch(void* const* d_in, const int* in_sizes, int n_in,
                              void* d_out, int out_size) {
    const float* pred = (const float*)d_in[0];
    const float* tgt  = (const float*)d_in[1];
    float* out = (float*)d_out;
    (void)in_sizes; (void)n_in; (void)out_size;

    dim3 mb(Wn, 2);
    mask_kernel<<<2 * Bn * NCH, mb>>>(pred, tgt);
    rowpass_kernel<<<Bn * Hn, Wn>>>(pred, tgt, out);
}

// round 10
// speedup vs baseline: 1.1516x; 1.1516x over previous
#include <cuda_runtime.h>
#include <math.h>

#define Bn 8
#define Hn 192
#define Wn 192
#define NTOT (Bn*Hn*Wn)
#define NCH 6                     // 192 rows = 6 x u32 words
#define BIGD (1 << 20)

typedef unsigned long long ull;

__device__ unsigned g_mask[2][Bn][NCH][Wn];   // fg bit per (row chunk, col)
__device__ int      g_hasany[2][Bn][NCH];
__device__ float    g_part[Bn*Hn];
__device__ unsigned g_count = 0;

// ---------------------------------------------------------------------------
// Kernel A: per-column fg bitmasks. Block = (tensor, b, 32-row chunk),
// blockDim (192,2): each thread builds 16 bits; halves composed via shared.
// ---------------------------------------------------------------------------
__global__ void mask_kernel(const float* __restrict__ pred,
                            const float* __restrict__ tgt) {
    const int blk = blockIdx.x;               // t*48 + b*6 + chunk
    const int t = blk / (Bn * NCH);
    const int r = blk % (Bn * NCH);
    const int b = r / NCH;
    const int chunk = r % NCH;
    const float* src = t ? tgt : pred;
    const int w = threadIdx.x;
    const int y = threadIdx.y;                // 0 = low 16 rows, 1 = high 16
    const int h0 = chunk * 32 + y * 16;

    unsigned part = 0;
    #pragma unroll
    for (int i = 0; i < 16; ++i) {
        float v = src[(b * Hn + h0 + i) * Wn + w];
        bool fg = t ? (v > 0.5f) : (v > 0.0f);   // sigmoid(v)>0.5 <=> v>0
        part |= (unsigned)fg << i;
    }

    __shared__ unsigned sm[Wn];
    if (y == 0) sm[w] = part;
    int any = __syncthreads_or(part != 0u);
    if (y == 1) g_mask[t][b][chunk][w] = sm[w] | (part << 16);
    if (w == 0 && y == 0) g_hasany[t][b][chunk] = any;
}

// ---------------------------------------------------------------------------
// Distance from row h (word c, bit position `bit`, both uniform per block)
// to the nearest set bit of the 192-bit mask (m0 lowest). All word selection
// done with uniform ternaries -> SEL, no dynamically indexed arrays.
// ---------------------------------------------------------------------------
__device__ __forceinline__ int nearest_set3(ull m0, ull m1, ull m2,
                                            int c, int bit) {
    ull a  = (c == 0) ? m0 : ((c == 1) ? m1 : m2);
    ull dn1 = (c == 0) ? m1 : ((c == 1) ? m2 : 0ULL);   // word above
    ull dn2 = (c == 0) ? m2 : 0ULL;                     // two above
    ull up1 = (c == 2) ? m1 : ((c == 1) ? m0 : 0ULL);   // word below
    ull up2 = (c == 2) ? m0 : 0ULL;                     // two below

    int down, up;
    ull x = a & (~0ULL << bit);                 // bits >= h within word c
    if (x)        down = __ffsll(x) - 1 - bit;
    else if (dn1) down = 64  + __ffsll(dn1) - 1 - bit;
    else if (dn2) down = 128 + __ffsll(dn2) - 1 - bit;
    else          down = BIGD;

    x = a << (63 - bit);                        // bits <= h shifted to MSB
    if (x)        up = __clzll(x);
    else if (up1) up = bit + 1  + __clzll(up1);
    else if (up2) up = bit + 65 + __clzll(up2);
    else          up = BIGD;

    return min(up, down);
}

// ---------------------------------------------------------------------------
// Kernel B: per-pixel the EDT identity holds: exactly one of (fg-EDT, bg-EDT)
// is nonzero (own-class term is 0 at q=p in both passes). So per tensor we do
// ONE column scan (opposite-class mask) and ONE windowed row-DT search, and
// field = sqrt(D_own). Pred+tgt searches share one d-loop with a joint break.
// ---------------------------------------------------------------------------
__global__ void rowpass_kernel(const float* __restrict__ pred,
                               const float* __restrict__ tgt,
                               float* __restrict__ out) {
    const int b = blockIdx.x / Hn;
    const int h = blockIdx.x % Hn;
    const int p = threadIdx.x;
    const int c = h >> 6, bit = h & 63;         // uniform per block

    __shared__ float ssq[4][Wn];                // [predFG, predBG, tgtFG, tgtBG]
    __shared__ float wsum[6];
    __shared__ int   s_last;

    // load 192-bit column masks (6 coalesced u32 loads per tensor)
    ull mp0, mp1, mp2, mt0, mt1, mt2;
    {
        const unsigned* gp = &g_mask[0][b][0][p];
        const unsigned* gt = &g_mask[1][b][0][p];
        mp0 = (ull)gp[0*Wn] | ((ull)gp[1*Wn] << 32);
        mp1 = (ull)gp[2*Wn] | ((ull)gp[3*Wn] << 32);
        mp2 = (ull)gp[4*Wn] | ((ull)gp[5*Wn] << 32);
        mt0 = (ull)gt[0*Wn] | ((ull)gt[1*Wn] << 32);
        mt1 = (ull)gt[2*Wn] | ((ull)gt[3*Wn] << 32);
        mt2 = (ull)gt[4*Wn] | ((ull)gt[5*Wn] << 32);
    }
    ull wp = (c == 0) ? mp0 : ((c == 1) ? mp1 : mp2);
    ull wt = (c == 0) ? mt0 : ((c == 1) ? mt1 : mt2);
    const bool fgP = (wp >> bit) & 1ULL;
    const bool fgT = (wt >> bit) & 1ULL;

    // column distance to nearest OPPOSITE-class pixel (complement if fg)
    int dP = nearest_set3(fgP ? ~mp0 : mp0, fgP ? ~mp1 : mp1,
                          fgP ? ~mp2 : mp2, c, bit);
    int dT = nearest_set3(fgT ? ~mt0 : mt0, fgT ? ~mt1 : mt1,
                          fgT ? ~mt2 : mt2, c, bit);
    float dsqP = (dP >= BIGD) ? 1.0e12f : (float)(dP * dP);
    float dsqT = (dT >= BIGD) ? 1.0e12f : (float)(dT * dT);
    ssq[0][p] = fgP ? dsqP : 0.0f;              // pred fg-EDT column dist^2
    ssq[1][p] = fgP ? 0.0f : dsqP;              // pred bg-EDT column dist^2
    ssq[2][p] = fgT ? dsqT : 0.0f;
    ssq[3][p] = fgT ? 0.0f : dsqT;
    __syncthreads();

    // exact min_q (p-q)^2 + s_q^2, own-class array only, joint early break.
    const float* spP = fgP ? ssq[0] : ssq[1];
    const float* spT = fgT ? ssq[2] : ssq[3];
    float bp = spP[p];
    float bt = spT[p];
    for (int d = 1; d < Wn; ++d) {
        float dd = (float)(d * d);
        if (dd >= fmaxf(bp, bt)) break;         // all further terms >= d^2
        int lo = p - d, hi = p + d;
        if (lo >= 0) {
            bp = fminf(bp, dd + spP[lo]);
            bt = fminf(bt, dd + spT[lo]);
        }
        if (hi < Wn) {
            bp = fminf(bp, dd + spP[hi]);
            bt = fminf(bt, dd + spT[hi]);
        }
    }

    int hp = 0, ht = 0;
    #pragma unroll
    for (int j = 0; j < NCH; ++j) {
        hp |= g_hasany[0][b][j];
        ht |= g_hasany[1][b][j];
    }

    // other-class D is exactly 0 -> field = sqrt(D_own)
    float pd = sqrtf(bp) * (float)hp;
    float td = sqrtf(bt) * (float)ht;

    const int idx = (b * Hn + h) * Wn + p;
    float x  = pred[idx];
    float tv = tgt[idx];
    float sg = 1.0f / (1.0f + expf(-x));
    float e  = sg - tv;
    e = e * e;

    float num = pd * pd + td * td;
    float den = pd + td;
    den = den * den;
    float v = e * (num / den);

    // deterministic block reduction
    #pragma unroll
    for (int o = 16; o > 0; o >>= 1)
        v += __shfl_down_sync(0xffffffffu, v, o);
    if ((p & 31) == 0) wsum[p >> 5] = v;
    __syncthreads();
    if (p == 0) {
        float s = 0.0f;
        #pragma unroll
        for (int i = 0; i < 6; ++i) s += wsum[i];
        g_part[blockIdx.x] = s;
        __threadfence();
        unsigned ticket = atomicAdd(&g_count, 1u);
        s_last = (ticket == (unsigned)(gridDim.x - 1));
    }
    __syncthreads();

    // last finishing block: deterministic fixed-order fp64 final reduction.
    if (s_last) {
        __shared__ double dsm[Wn];
        double s = 0.0;
        for (int i = p; i < Bn * Hn; i += Wn)
            s += (double)g_part[i];
        dsm[p] = s;
        __syncthreads();
        #pragma unroll
        for (int o = 96; o >= 3; o >>= 1) {     // 192->96->...->3
            if (p < o) dsm[p] += dsm[p + o];
            __syncthreads();
        }
        if (p == 0) {
            double tot = dsm[0] + dsm[1] + dsm[2];
            out[0] = (float)(tot / (double)NTOT);
            g_count = 0;
        }
    }
}

extern "C" void kernel_launch(void* const* d_in, const int* in_sizes, int n_in,
                              void* d_out, int out_size) {
    const float* pred = (const float*)d_in[0];
    const float* tgt  = (const float*)d_in[1];
    float* out = (float*)d_out;
    (void)in_sizes; (void)n_in; (void)out_size;

    dim3 mb(Wn, 2);
    mask_kernel<<<2 * Bn * NCH, mb>>>(pred, tgt);
    rowpass_kernel<<<Bn * Hn, Wn>>>(pred, tgt, out);
}

// round 11
// speedup vs baseline: 1.2712x; 1.1038x over previous
#include <cuda_runtime.h>
#include <math.h>

#define Bn 8
#define Hn 192
#define Wn 192
#define NTOT (Bn*Hn*Wn)
#define NCH 6                     // 192 rows = 6 x u32 words
#define BIGD (1 << 20)

typedef unsigned long long ull;

__device__ unsigned g_mask[2][Bn][NCH][Wn];   // fg bit per (row chunk, col)
__device__ int      g_hasany[2][Bn][NCH];
__device__ float    g_part[Bn*Hn];
__device__ unsigned g_count = 0;

// ---------------------------------------------------------------------------
// Kernel A: per-column fg bitmasks. Block = (tensor, b, 32-row chunk),
// blockDim (192,2): each thread builds 16 bits; halves composed via shared.
// ---------------------------------------------------------------------------
__global__ void mask_kernel(const float* __restrict__ pred,
                            const float* __restrict__ tgt) {
    const int blk = blockIdx.x;               // t*48 + b*6 + chunk
    const int t = blk / (Bn * NCH);
    const int r = blk % (Bn * NCH);
    const int b = r / NCH;
    const int chunk = r % NCH;
    const float* src = t ? tgt : pred;
    const int w = threadIdx.x;
    const int y = threadIdx.y;                // 0 = low 16 rows, 1 = high 16
    const int h0 = chunk * 32 + y * 16;

    unsigned part = 0;
    #pragma unroll
    for (int i = 0; i < 16; ++i) {
        float v = src[(b * Hn + h0 + i) * Wn + w];
        bool fg = t ? (v > 0.5f) : (v > 0.0f);   // sigmoid(v)>0.5 <=> v>0
        part |= (unsigned)fg << i;
    }

    __shared__ unsigned sm[Wn];
    if (y == 0) sm[w] = part;
    int any = __syncthreads_or(part != 0u);
    if (y == 1) g_mask[t][b][chunk][w] = sm[w] | (part << 16);
    if (w == 0 && y == 0) g_hasany[t][b][chunk] = any;
}

// ---------------------------------------------------------------------------
// Distance from row h (word c, bit position `bit`, uniform per block) to the
// nearest set bit of the 192-bit mask (m0 lowest). Word selection via uniform
// ternaries -> SEL, no dynamically indexed register arrays (no local memory).
// ---------------------------------------------------------------------------
__device__ __forceinline__ int nearest_set3(ull m0, ull m1, ull m2,
                                            int c, int bit) {
    ull a   = (c == 0) ? m0 : ((c == 1) ? m1 : m2);
    ull dn1 = (c == 0) ? m1 : ((c == 1) ? m2 : 0ULL);
    ull dn2 = (c == 0) ? m2 : 0ULL;
    ull up1 = (c == 2) ? m1 : ((c == 1) ? m0 : 0ULL);
    ull up2 = (c == 2) ? m0 : 0ULL;

    int down, up;
    ull x = a & (~0ULL << bit);                 // bits >= h within word c
    if (x)        down = __ffsll(x) - 1 - bit;
    else if (dn1) down = 64  + __ffsll(dn1) - 1 - bit;
    else if (dn2) down = 128 + __ffsll(dn2) - 1 - bit;
    else          down = BIGD;

    x = a << (63 - bit);                        // bits <= h shifted to MSB
    if (x)        up = __clzll(x);
    else if (up1) up = bit + 1  + __clzll(up1);
    else if (up2) up = bit + 65 + __clzll(up2);
    else          up = BIGD;

    return min(up, down);
}

// ---------------------------------------------------------------------------
// Kernel B: EDT identity (one of fg/bg EDT is 0 per pixel) -> one column scan
// + one windowed row-DT per tensor. Shared arrays padded with 1e12 on both
// sides so the search loop has NO bounds checks: 4 independent LDS per iter.
// ---------------------------------------------------------------------------
__global__ void rowpass_kernel(const float* __restrict__ pred,
                               const float* __restrict__ tgt,
                               float* __restrict__ out) {
    const int b = blockIdx.x / Hn;
    const int h = blockIdx.x % Hn;
    const int p = threadIdx.x;
    const int c = h >> 6, bit = h & 63;         // uniform per block

    __shared__ float ssq[4][3 * Wn];            // [class][pad | data | pad]
    __shared__ float wsum[6];
    __shared__ int   s_last;

    // prefetch loss inputs early: global latency hides under scan + DT loop
    const int idx = (b * Hn + h) * Wn + p;
    const float x  = pred[idx];
    const float tv = tgt[idx];

    // pad borders (value larger than any real candidate, = sentinel)
    #pragma unroll
    for (int k = 0; k < 4; ++k) {
        ssq[k][p]          = 1.0e12f;
        ssq[k][p + 2*Wn]   = 1.0e12f;
    }

    // load 192-bit column masks (6 coalesced u32 loads per tensor)
    ull mp0, mp1, mp2, mt0, mt1, mt2;
    {
        const unsigned* gp = &g_mask[0][b][0][p];
        const unsigned* gt = &g_mask[1][b][0][p];
        mp0 = (ull)gp[0*Wn] | ((ull)gp[1*Wn] << 32);
        mp1 = (ull)gp[2*Wn] | ((ull)gp[3*Wn] << 32);
        mp2 = (ull)gp[4*Wn] | ((ull)gp[5*Wn] << 32);
        mt0 = (ull)gt[0*Wn] | ((ull)gt[1*Wn] << 32);
        mt1 = (ull)gt[2*Wn] | ((ull)gt[3*Wn] << 32);
        mt2 = (ull)gt[4*Wn] | ((ull)gt[5*Wn] << 32);
    }
    ull wp = (c == 0) ? mp0 : ((c == 1) ? mp1 : mp2);
    ull wt = (c == 0) ? mt0 : ((c == 1) ? mt1 : mt2);
    const bool fgP = (wp >> bit) & 1ULL;
    const bool fgT = (wt >> bit) & 1ULL;

    // column distance to nearest OPPOSITE-class pixel
    int dP = nearest_set3(fgP ? ~mp0 : mp0, fgP ? ~mp1 : mp1,
                          fgP ? ~mp2 : mp2, c, bit);
    int dT = nearest_set3(fgT ? ~mt0 : mt0, fgT ? ~mt1 : mt1,
                          fgT ? ~mt2 : mt2, c, bit);
    float dsqP = (dP >= BIGD) ? 1.0e12f : (float)(dP * dP);
    float dsqT = (dT >= BIGD) ? 1.0e12f : (float)(dT * dT);
    ssq[0][Wn + p] = fgP ? dsqP : 0.0f;         // pred fg-EDT col dist^2
    ssq[1][Wn + p] = fgP ? 0.0f : dsqP;         // pred bg-EDT col dist^2
    ssq[2][Wn + p] = fgT ? dsqT : 0.0f;
    ssq[3][Wn + p] = fgT ? 0.0f : dsqT;
    __syncthreads();

    // exact min_q (p-q)^2 + s_q^2 over own-class array; padded -> no bounds.
    const float* aP = (fgP ? ssq[0] : ssq[1]) + Wn + p;
    const float* aT = (fgT ? ssq[2] : ssq[3]) + Wn + p;
    float bp = aP[0];
    float bt = aT[0];
    float bmax = fmaxf(bp, bt);
    for (int d = 1; d < Wn; ++d) {
        float dd = (float)(d * d);
        if (dd >= bmax) break;                  // all further terms >= d^2
        float p0 = aP[-d], p1 = aP[d];
        float t0 = aT[-d], t1 = aT[d];
        bp = fminf(bp, dd + fminf(p0, p1));
        bt = fminf(bt, dd + fminf(t0, t1));
        bmax = fmaxf(bp, bt);
    }

    int hp = 0, ht = 0;
    #pragma unroll
    for (int j = 0; j < NCH; ++j) {
        hp |= g_hasany[0][b][j];
        ht |= g_hasany[1][b][j];
    }

    // other-class D is exactly 0 -> field = sqrt(D_own)
    float pd = sqrtf(bp) * (float)hp;
    float td = sqrtf(bt) * (float)ht;

    float sg = 1.0f / (1.0f + expf(-x));
    float e  = sg - tv;
    e = e * e;

    float num = pd * pd + td * td;
    float den = pd + td;
    den = den * den;
    float v = e * (num / den);

    // deterministic block reduction
    #pragma unroll
    for (int o = 16; o > 0; o >>= 1)
        v += __shfl_down_sync(0xffffffffu, v, o);
    if ((p & 31) == 0) wsum[p >> 5] = v;
    __syncthreads();
    if (p == 0) {
        float s = 0.0f;
        #pragma unroll
        for (int i = 0; i < 6; ++i) s += wsum[i];
        g_part[blockIdx.x] = s;
        __threadfence();
        unsigned ticket = atomicAdd(&g_count, 1u);
        s_last = (ticket == (unsigned)(gridDim.x - 1));
    }
    __syncthreads();

    // last finishing block: deterministic fixed-order fp64 final reduction.
    if (s_last) {
        __shared__ double dsm[Wn];
        double s = 0.0;
        for (int i = p; i < Bn * Hn; i += Wn)
            s += (double)g_part[i];
        dsm[p] = s;
        __syncthreads();
        #pragma unroll
        for (int o = 96; o >= 3; o >>= 1) {     // 192->96->...->3
            if (p < o) dsm[p] += dsm[p + o];
            __syncthreads();
        }
        if (p == 0) {
            double tot = dsm[0] + dsm[1] + dsm[2];
            out[0] = (float)(tot / (double)NTOT);
            g_count = 0;
        }
    }
}

extern "C" void kernel_launch(void* const* d_in, const int* in_sizes, int n_in,
                              void* d_out, int out_size) {
    const float* pred = (const float*)d_in[0];
    const float* tgt  = (const float*)d_in[1];
    float* out = (float*)d_out;
    (void)in_sizes; (void)n_in; (void)out_size;

    dim3 mb(Wn, 2);
    mask_kernel<<<2 * Bn * NCH, mb>>>(pred, tgt);
    rowpass_kernel<<<Bn * Hn, Wn>>>(pred, tgt, out);
}